// round 2
// baseline (speedup 1.0000x reference)
#include <cuda_runtime.h>

#define NN 50000
#define NE 1600000
#define TOT (NE + NN)
#define DIN 128
#define DH  64
#define SCAN_B 512
#define NB_SCAN 98   // ceil(NN/512)
#define BN_EPS 1e-5f

// ---------------- scratch ----------------
__device__ int   g_src[NE];
__device__ int   g_dst[NE];
__device__ float g_w[NE];
__device__ float g_deg[NN];
__device__ float g_dinv[NN];
__device__ int   g_cnt[NN];
__device__ int   g_cur[NN];
__device__ int   g_rowstart[NN + 1];
__device__ int   g_bsum[NB_SCAN];
__device__ __align__(16) int2  g_cv[TOT];      // (col, val-as-bits)
__device__ __align__(16) float g_h[NN * DH];
__device__ __align__(16) float g_agg[NN * DH];
__device__ float g_sum[DH], g_sq[DH];
__device__ __align__(16) float g_scale[DH];
__device__ __align__(16) float g_shift[DH];
__device__ int   g_is64;

// ---------------- init ----------------
__global__ void k_init() {
    int i = blockIdx.x * blockDim.x + threadIdx.x;
    if (i < NN) {
        g_deg[i] = 1.0f;   // self-loop weight 1
        g_cnt[i] = 1;      // self-loop entry
        g_cur[i] = 0;
    }
    if (i < DH) { g_sum[i] = 0.f; g_sq[i] = 0.f; }
    if (i == 0) g_is64 = 1;
}

// Detect edge_index dtype: view as int32; if stored as little-endian int64 with
// values < 2^31, every odd int32 word is 0. For true int32 data the odd words
// are random node indices (P(all 256 samples == 0) ~ 0).
__global__ void k_probe(const int* __restrict__ ei32) {
    int i = threadIdx.x;                    // 256 threads
    int k = i * (NE / 256);                 // spread samples across first row
    if (ei32[2 * k + 1] != 0) g_is64 = 0;   // benign race: only writes 0
}

// ---------------- edge prep: mix weights, degree, counts ----------------
__global__ void k_edge_prep(const void* __restrict__ ei,
                            const float* __restrict__ wsc,
                            const float* __restrict__ wfc,
                            const float* __restrict__ alpha) {
    int e = blockIdx.x * blockDim.x + threadIdx.x;
    if (e >= NE) return;
    float a = 1.f / (1.f + __expf(-__ldg(alpha)));
    int s, d;
    if (g_is64) {
        const long long* p = (const long long*)ei;
        s = (int)__ldg(&p[e]);
        d = (int)__ldg(&p[NE + e]);
    } else {
        const int* p = (const int*)ei;
        s = __ldg(&p[e]);
        d = __ldg(&p[NE + e]);
    }
    s = min(max(s, 0), NN - 1);
    d = min(max(d, 0), NN - 1);
    float w = a * __ldg(&wsc[e]) + (1.f - a) * __ldg(&wfc[e]);
    g_src[e] = s; g_dst[e] = d; g_w[e] = w;
    atomicAdd(&g_deg[d], w);
    atomicAdd(&g_cnt[d], 1);
}

__global__ void k_dinv() {
    int i = blockIdx.x * blockDim.x + threadIdx.x;
    if (i < NN) g_dinv[i] = rsqrtf(g_deg[i]);   // deg >= 1 (self loop)
}

// ---------------- exclusive scan of g_cnt -> g_rowstart ----------------
__global__ void k_scan1() {
    __shared__ int s[SCAN_B];
    int t = threadIdx.x;
    int i = blockIdx.x * SCAN_B + t;
    int v = (i < NN) ? g_cnt[i] : 0;
    s[t] = v; __syncthreads();
    for (int off = 1; off < SCAN_B; off <<= 1) {
        int u = (t >= off) ? s[t - off] : 0;
        __syncthreads();
        s[t] += u; __syncthreads();
    }
    if (i < NN) g_rowstart[i] = s[t] - v;          // exclusive, pre-offset
    if (t == SCAN_B - 1) g_bsum[blockIdx.x] = s[t];
}
__global__ void k_scan2() {
    __shared__ int s[128];
    int t = threadIdx.x;
    int v = (t < NB_SCAN) ? g_bsum[t] : 0;
    s[t] = v; __syncthreads();
    for (int off = 1; off < 128; off <<= 1) {
        int u = (t >= off) ? s[t - off] : 0;
        __syncthreads();
        s[t] += u; __syncthreads();
    }
    if (t < NB_SCAN) g_bsum[t] = s[t] - v;         // exclusive block offsets
}
__global__ void k_scan3() {
    int i = blockIdx.x * SCAN_B + threadIdx.x;
    if (i < NN) g_rowstart[i] += g_bsum[i >> 9];
    if (i == 0) g_rowstart[NN] = TOT;
}

// ---------------- CSR fill ----------------
__global__ void k_fill_edges() {
    int e = blockIdx.x * blockDim.x + threadIdx.x;
    if (e >= NE) return;
    int d = g_dst[e], s = g_src[e];
    int p = g_rowstart[d] + atomicAdd(&g_cur[d], 1);
    float nv = g_dinv[s] * g_w[e] * g_dinv[d];
    g_cv[p] = make_int2(s, __float_as_int(nv));
}
__global__ void k_fill_self() {
    int i = blockIdx.x * blockDim.x + threadIdx.x;
    if (i >= NN) return;
    int p = g_rowstart[i] + atomicAdd(&g_cur[i], 1);
    float di = g_dinv[i];
    g_cv[p] = make_int2(i, __float_as_int(di * di));
}

// ---------------- GEMM1: g_h = x[N,128] @ W1[128,64] ----------------
__global__ void __launch_bounds__(256) k_gemm1(const float* __restrict__ x,
                                               const float* __restrict__ W1) {
    __shared__ __align__(16) float sW[DIN * DH];      // 32 KB
    for (int i = threadIdx.x; i < DIN * DH; i += 256) sW[i] = W1[i];
    __syncthreads();
    int warp = threadIdx.x >> 5, lane = threadIdx.x & 31;
    int nbase = blockIdx.x * 32 + warp * 4;
    if (nbase >= NN) return;
    int n0 = nbase, n1 = min(nbase + 1, NN - 1), n2 = min(nbase + 2, NN - 1), n3 = min(nbase + 3, NN - 1);
    const float4* x0 = (const float4*)(x + (size_t)n0 * DIN);
    const float4* x1 = (const float4*)(x + (size_t)n1 * DIN);
    const float4* x2 = (const float4*)(x + (size_t)n2 * DIN);
    const float4* x3 = (const float4*)(x + (size_t)n3 * DIN);
    float2 a0 = {0.f,0.f}, a1 = {0.f,0.f}, a2 = {0.f,0.f}, a3 = {0.f,0.f};
    #pragma unroll
    for (int kk = 0; kk < DIN / 4; ++kk) {
        float ra[4], rb[4], rc[4], rd[4];
        *(float4*)ra = __ldg(x0 + kk);
        *(float4*)rb = __ldg(x1 + kk);
        *(float4*)rc = __ldg(x2 + kk);
        *(float4*)rd = __ldg(x3 + kk);
        #pragma unroll
        for (int u = 0; u < 4; ++u) {
            float2 w = *(const float2*)&sW[(4 * kk + u) * DH + 2 * lane];
            a0.x += ra[u] * w.x; a0.y += ra[u] * w.y;
            a1.x += rb[u] * w.x; a1.y += rb[u] * w.y;
            a2.x += rc[u] * w.x; a2.y += rc[u] * w.y;
            a3.x += rd[u] * w.x; a3.y += rd[u] * w.y;
        }
    }
    *(float2*)&g_h[(size_t)n0 * DH + 2 * lane] = a0;
    if (nbase + 1 < NN) *(float2*)&g_h[(size_t)n1 * DH + 2 * lane] = a1;
    if (nbase + 2 < NN) *(float2*)&g_h[(size_t)n2 * DH + 2 * lane] = a2;
    if (nbase + 3 < NN) *(float2*)&g_h[(size_t)n3 * DH + 2 * lane] = a3;
}

// ---------------- CSR gather aggregation: g_agg = A_norm @ g_h + bias ----------------
__global__ void __launch_bounds__(256) k_agg(const float* __restrict__ bias) {
    int gw = (blockIdx.x * 256 + threadIdx.x) >> 5;
    int lane = threadIdx.x & 31;
    if (gw >= NN) return;
    int beg = g_rowstart[gw], end = g_rowstart[gw + 1];
    const float2* hp = (const float2*)g_h;
    float2 acc = {0.f, 0.f};
    int j = beg;
    for (; j + 4 <= end; j += 4) {
        int2 c0 = g_cv[j], c1 = g_cv[j + 1], c2 = g_cv[j + 2], c3 = g_cv[j + 3];
        float2 h0 = __ldg(&hp[(size_t)c0.x * 32 + lane]);
        float2 h1 = __ldg(&hp[(size_t)c1.x * 32 + lane]);
        float2 h2 = __ldg(&hp[(size_t)c2.x * 32 + lane]);
        float2 h3 = __ldg(&hp[(size_t)c3.x * 32 + lane]);
        float v0 = __int_as_float(c0.y), v1 = __int_as_float(c1.y);
        float v2 = __int_as_float(c2.y), v3 = __int_as_float(c3.y);
        acc.x += v0 * h0.x; acc.y += v0 * h0.y;
        acc.x += v1 * h1.x; acc.y += v1 * h1.y;
        acc.x += v2 * h2.x; acc.y += v2 * h2.y;
        acc.x += v3 * h3.x; acc.y += v3 * h3.y;
    }
    for (; j < end; ++j) {
        int2 c = g_cv[j];
        float2 hv = __ldg(&hp[(size_t)c.x * 32 + lane]);
        float v = __int_as_float(c.y);
        acc.x += v * hv.x; acc.y += v * hv.y;
    }
    float2 bv = *(const float2*)&bias[2 * lane];
    acc.x += bv.x; acc.y += bv.y;
    *(float2*)&g_agg[(size_t)gw * DH + 2 * lane] = acc;
}

// ---------------- column stats over g_agg ----------------
__global__ void __launch_bounds__(256) k_stats() {
    int c = threadIdx.x & 63;
    int rg = (blockIdx.x * blockDim.x + threadIdx.x) >> 6;
    int stride = (gridDim.x * blockDim.x) >> 6;
    float s = 0.f, q = 0.f;
    for (int r = rg; r < NN; r += stride) {
        float v = g_agg[(size_t)r * DH + c];
        s += v; q += v * v;
    }
    atomicAdd(&g_sum[c], s);
    atomicAdd(&g_sq[c], q);
}

__global__ void k_bnparam(const float* __restrict__ gamma, const float* __restrict__ beta) {
    int c = threadIdx.x;
    if (c >= DH) return;
    float mean = g_sum[c] * (1.f / NN);
    float var  = g_sq[c] * (1.f / NN) - mean * mean;
    float inv  = rsqrtf(var + BN_EPS);
    float sc   = __ldg(&gamma[c]) * inv;
    g_scale[c] = sc;
    g_shift[c] = __ldg(&beta[c]) - mean * sc;
    g_sum[c] = 0.f; g_sq[c] = 0.f;   // ready for next stats pass
}

// ---------------- GEMM2: g_h = relu(bn(g_agg)) @ W2[64,64] ----------------
__global__ void __launch_bounds__(256) k_gemm2(const float* __restrict__ W2) {
    __shared__ __align__(16) float sW[DH * DH];       // 16 KB
    __shared__ __align__(16) float ssc[DH];
    __shared__ __align__(16) float ssh[DH];
    for (int i = threadIdx.x; i < DH * DH; i += 256) sW[i] = W2[i];
    if (threadIdx.x < DH) { ssc[threadIdx.x] = g_scale[threadIdx.x]; ssh[threadIdx.x] = g_shift[threadIdx.x]; }
    __syncthreads();
    int warp = threadIdx.x >> 5, lane = threadIdx.x & 31;
    int nbase = blockIdx.x * 32 + warp * 4;
    if (nbase >= NN) return;
    int n0 = nbase, n1 = min(nbase + 1, NN - 1), n2 = min(nbase + 2, NN - 1), n3 = min(nbase + 3, NN - 1);
    const float4* x0 = (const float4*)(g_agg + (size_t)n0 * DH);
    const float4* x1 = (const float4*)(g_agg + (size_t)n1 * DH);
    const float4* x2 = (const float4*)(g_agg + (size_t)n2 * DH);
    const float4* x3 = (const float4*)(g_agg + (size_t)n3 * DH);
    float2 a0 = {0.f,0.f}, a1 = {0.f,0.f}, a2 = {0.f,0.f}, a3 = {0.f,0.f};
    #pragma unroll
    for (int kk = 0; kk < DH / 4; ++kk) {
        float ra[4], rb[4], rc[4], rd[4];
        *(float4*)ra = __ldg(x0 + kk);
        *(float4*)rb = __ldg(x1 + kk);
        *(float4*)rc = __ldg(x2 + kk);
        *(float4*)rd = __ldg(x3 + kk);
        float scs[4], shs[4];
        *(float4*)scs = *(float4*)&ssc[4 * kk];
        *(float4*)shs = *(float4*)&ssh[4 * kk];
        #pragma unroll
        for (int u = 0; u < 4; ++u) {
            float va = fmaxf(fmaf(ra[u], scs[u], shs[u]), 0.f);
            float vb = fmaxf(fmaf(rb[u], scs[u], shs[u]), 0.f);
            float vc = fmaxf(fmaf(rc[u], scs[u], shs[u]), 0.f);
            float vd = fmaxf(fmaf(rd[u], scs[u], shs[u]), 0.f);
            float2 w = *(const float2*)&sW[(4 * kk + u) * DH + 2 * lane];
            a0.x += va * w.x; a0.y += va * w.y;
            a1.x += vb * w.x; a1.y += vb * w.y;
            a2.x += vc * w.x; a2.y += vc * w.y;
            a3.x += vd * w.x; a3.y += vd * w.y;
        }
    }
    *(float2*)&g_h[(size_t)n0 * DH + 2 * lane] = a0;
    if (nbase + 1 < NN) *(float2*)&g_h[(size_t)n1 * DH + 2 * lane] = a1;
    if (nbase + 2 < NN) *(float2*)&g_h[(size_t)n2 * DH + 2 * lane] = a2;
    if (nbase + 3 < NN) *(float2*)&g_h[(size_t)n3 * DH + 2 * lane] = a3;
}

// ---------------- final: out = relu(bn(g_agg)) ----------------
__global__ void k_final(float* __restrict__ out) {
    int idx = blockIdx.x * blockDim.x + threadIdx.x;   // over NN*16 float4s
    if (idx >= NN * (DH / 4)) return;
    float4 v = ((const float4*)g_agg)[idx];
    int cb = (idx & (DH / 4 - 1)) * 4;
    v.x = fmaxf(fmaf(v.x, g_scale[cb + 0], g_shift[cb + 0]), 0.f);
    v.y = fmaxf(fmaf(v.y, g_scale[cb + 1], g_shift[cb + 1]), 0.f);
    v.z = fmaxf(fmaf(v.z, g_scale[cb + 2], g_shift[cb + 2]), 0.f);
    v.w = fmaxf(fmaf(v.w, g_scale[cb + 3], g_shift[cb + 3]), 0.f);
    ((float4*)out)[idx] = v;
}

// ---------------- launch ----------------
extern "C" void kernel_launch(void* const* d_in, const int* in_sizes, int n_in,
                              void* d_out, int out_size) {
    const float* x      = (const float*)d_in[0];
    const void*  ei_sc  = d_in[1];
    const float* wsc    = (const float*)d_in[2];
    // d_in[3] = edge_index_fc (unused by the reference math)
    const float* wfc    = (const float*)d_in[4];
    const float* alpha  = (const float*)d_in[5];
    const float* W1     = (const float*)d_in[6];
    const float* b1     = (const float*)d_in[7];
    const float* W2     = (const float*)d_in[8];
    const float* b2     = (const float*)d_in[9];
    const float* gamma1 = (const float*)d_in[10];
    const float* beta1  = (const float*)d_in[11];
    const float* gamma2 = (const float*)d_in[12];
    const float* beta2  = (const float*)d_in[13];
    float*       out    = (float*)d_out;

    const int TB = 256;
    // preprocessing
    k_init<<<(NN + TB - 1) / TB, TB>>>();
    k_probe<<<1, 256>>>((const int*)ei_sc);
    k_edge_prep<<<(NE + TB - 1) / TB, TB>>>(ei_sc, wsc, wfc, alpha);
    k_dinv<<<(NN + TB - 1) / TB, TB>>>();
    k_scan1<<<NB_SCAN, SCAN_B>>>();
    k_scan2<<<1, 128>>>();
    k_scan3<<<NB_SCAN, SCAN_B>>>();
    k_fill_edges<<<(NE + TB - 1) / TB, TB>>>();
    k_fill_self<<<(NN + TB - 1) / TB, TB>>>();
    // layer 1
    k_gemm1<<<(NN + 31) / 32, TB>>>(x, W1);
    k_agg<<<(NN * 32 + TB - 1) / TB, TB>>>(b1);
    k_stats<<<128, TB>>>();
    k_bnparam<<<1, 64>>>(gamma1, beta1);
    // layer 2 (BN+ReLU fused into GEMM2 input path)
    k_gemm2<<<(NN + 31) / 32, TB>>>(W2);
    k_agg<<<(NN * 32 + TB - 1) / TB, TB>>>(b2);
    k_stats<<<128, TB>>>();
    k_bnparam<<<1, 64>>>(gamma2, beta2);
    k_final<<<(NN * (DH / 4) + TB - 1) / TB, TB>>>(out);
}